// round 1
// baseline (speedup 1.0000x reference)
#include <cuda_runtime.h>
#include <cuda_bf16.h>
#include <cfloat>
#include <cub/block/block_radix_sort.cuh>

// Problem constants
constexpr int L   = 8192;   // row length
constexpr int NB  = 65;     // bins / quantile edges
constexpr int NT  = 512;    // threads per block
constexpr int IPT = 16;     // items per thread (NT*IPT == L)

using Sorter = cub::BlockRadixSort<float, NT, IPT>;

// Dynamic shared memory layout:
//   region A: union of { Sorter::TempStorage , float sorted[L] }
//   region B: unsigned hist[NB*NB]
constexpr size_t A_RAW   = (sizeof(typename Sorter::TempStorage) > (size_t)L * sizeof(float))
                               ? sizeof(typename Sorter::TempStorage)
                               : (size_t)L * sizeof(float);
constexpr size_t A_BYTES = (A_RAW + 127) & ~(size_t)127;
constexpr size_t SMEM_TOTAL = A_BYTES + (size_t)NB * NB * sizeof(unsigned);

__global__ __launch_bounds__(NT) void mtf_kernel(const float* __restrict__ x,
                                                 float* __restrict__ out)
{
    extern __shared__ char smem_raw[];
    float*    sorted = reinterpret_cast<float*>(smem_raw);
    unsigned* hist   = reinterpret_cast<unsigned*>(smem_raw + A_BYTES);

    __shared__ float s_edges[NB];
    __shared__ int   s_first, s_last;
    __shared__ unsigned char s_firstbin[NT];

    const int row = blockIdx.x;
    const float* __restrict__ xr = x + (size_t)row * L;
    const int t = threadIdx.x;

    if (t == 0) { s_first = L; s_last = -1; }
    // zero histogram
    for (int i = t; i < NB * NB; i += NT) hist[i] = 0u;
    __syncthreads();

    // ---- Phase A: load row (blocked), find first/last nonzero ----
    float keys[IPT];
    int lmin = L, lmax = -1;
#pragma unroll
    for (int i = 0; i < IPT; ++i) {
        int idx = t * IPT + i;
        float v = xr[idx];
        keys[i] = v;
        if (v != 0.0f) {
            if (idx < lmin) lmin = idx;
            if (idx > lmax) lmax = idx;
        }
    }
    if (lmin < L)  atomicMin(&s_first, lmin);
    if (lmax >= 0) atomicMax(&s_last,  lmax);
    __syncthreads();

    const int first = s_first;
    const int last  = s_last;
    const bool any  = (last >= 0);
    const int m     = any ? (last - first + 1) : 0;

    // ---- Phase B: mask out-of-range -> FLT_MAX, block radix sort ----
#pragma unroll
    for (int i = 0; i < IPT; ++i) {
        int idx = t * IPT + i;
        if (!(any && idx >= first && idx <= last)) keys[i] = FLT_MAX;
    }
    __syncthreads();
    Sorter(*reinterpret_cast<typename Sorter::TempStorage*>(smem_raw)).Sort(keys);
    __syncthreads();
#pragma unroll
    for (int i = 0; i < IPT; ++i) sorted[t * IPT + i] = keys[i];
    __syncthreads();

    // ---- Phase C: 65 quantile edges (fp32 math mirrors jnp exactly) ----
    if (t < NB) {
        float q;
        if (m > 0) {
            const float step = 1.0f / 65.0f;           // linspace step in fp32
            float qlev = (float)t * step;
            float pos  = qlev * (float)(m - 1);
            int   lo   = (int)floorf(pos);
            int   hi   = (int)ceilf(pos);
            float frac = pos - (float)lo;
            float vlo  = sorted[lo];
            float vhi  = sorted[hi];
            q = vlo + frac * (vhi - vlo);
        } else {
            q = 0.0f;
        }
        s_edges[t] = q;
    }
    __syncthreads();

    // ---- Phase D: bin every value (upper_bound over edges), transitions ----
    int binreg[IPT];
#pragma unroll
    for (int i = 0; i < IPT; ++i) {
        int idx = t * IPT + i;
        float v = xr[idx];
        // searchsorted(edges, v, side='right') == count(edges <= v)
        int lo = 0, hi = NB;
        while (lo < hi) {
            int mid = (lo + hi) >> 1;
            if (s_edges[mid] <= v) lo = mid + 1; else hi = mid;
        }
        int b = lo;
        if (b > NB - 1) b = NB - 1;
        binreg[i] = b;
    }
    s_firstbin[t] = (unsigned char)binreg[0];
    __syncthreads();

    // 15 in-register transition pairs per thread
#pragma unroll
    for (int i = 0; i < IPT - 1; ++i)
        atomicAdd(&hist[binreg[i] * NB + binreg[i + 1]], 1u);
    // boundary pair to the next thread's first element
    if (t < NT - 1)
        atomicAdd(&hist[binreg[IPT - 1] * NB + (int)s_firstbin[t + 1]], 1u);
    __syncthreads();

    // ---- Phase E: normalize + store ----
    const float inv = 1.0f / (float)(L - 1);
    float* outr = out + (size_t)row * NB * NB;
    for (int i = t; i < NB * NB; i += NT)
        outr[i] = (float)hist[i] * inv;
}

extern "C" void kernel_launch(void* const* d_in, const int* in_sizes, int n_in,
                              void* d_out, int out_size)
{
    const float* x = (const float*)d_in[0];
    float* out = (float*)d_out;
    const int rows = in_sizes[0] / L;   // 512*4 = 2048

    cudaFuncSetAttribute(mtf_kernel,
                         cudaFuncAttributeMaxDynamicSharedMemorySize,
                         (int)SMEM_TOTAL);
    mtf_kernel<<<rows, NT, SMEM_TOTAL>>>(x, out);
}